// round 1
// baseline (speedup 1.0000x reference)
#include <cuda_runtime.h>
#include <math.h>

#define SIZE   1024
#define INPUT  1024
#define CTX    512
#define CMS    6
#define NSLOT  64
#define BATCH  128
#define SPER   8      // neurons per block in ctx kernel

// Scratch (device globals — no allocation allowed)
__device__ float g_logT[BATCH * INPUT];   // logits transposed: [b][i]
__device__ int   g_ctx [SIZE * BATCH];    // context index:     [s][b]

// ---------------------------------------------------------------------------
// Kernel 1: transpose logits (INPUT, BATCH) -> (BATCH, INPUT) for coalesced dots
// ---------------------------------------------------------------------------
__global__ void transpose_logits_k(const float* __restrict__ in) {
    __shared__ float tile[32][33];
    int i0 = blockIdx.x * 32;
    int b0 = blockIdx.y * 32;
    int x = threadIdx.x, y = threadIdx.y;
    #pragma unroll
    for (int j = 0; j < 32; j += 8)
        tile[y + j][x] = in[(size_t)(i0 + y + j) * BATCH + (b0 + x)];
    __syncthreads();
    #pragma unroll
    for (int j = 0; j < 32; j += 8)
        g_logT[(size_t)(b0 + y + j) * INPUT + (i0 + x)] = tile[x][y + j];
}

// ---------------------------------------------------------------------------
// Kernel 2: context hashing.
// projected[s,m,b] = sum_c proj[s,m,c] * ctx[c,b];  bit m = projected > pbias[s,m]
// Block handles SPER neurons; 256 threads = (b in [0,128)) x (h in {0,1} c-halves).
// ---------------------------------------------------------------------------
__global__ __launch_bounds__(256) void ctx_k(
        const float* __restrict__ proj,
        const float* __restrict__ pbias,
        const float* __restrict__ ctxin) {
    // pool layout: [0, 8448) ctx tile (2 halves)[128 b][33 c-pad]
    //              [8448, 11520) proj tile (2 halves)[SPER][CMS][32]
    __shared__ float pool[11520];
    const int tid = threadIdx.x;
    const int b = tid & 127;
    const int h = tid >> 7;
    const int s0 = blockIdx.x * SPER;

    float acc[SPER][CMS];
    #pragma unroll
    for (int sl = 0; sl < SPER; sl++)
        #pragma unroll
        for (int m = 0; m < CMS; m++) acc[sl][m] = 0.0f;

    for (int r = 0; r < 8; r++) {
        const int cbase = h * 256 + r * 32;
        // load ctx tile: 32 c-rows x 128 b (coalesced across b)
        #pragma unroll 4
        for (int c = 0; c < 32; c++)
            pool[h * (128 * 33) + b * 33 + c] =
                ctxin[(size_t)(cbase + c) * BATCH + b];
        // load proj tile for this half: SPER*CMS*32 floats by 128 threads
        for (int l = b; l < SPER * CMS * 32; l += 128) {
            int sl = l / (CMS * 32);
            int m  = (l / 32) % CMS;
            int c  = l & 31;
            pool[8448 + ((h * SPER + sl) * CMS + m) * 32 + c] =
                proj[((size_t)(s0 + sl) * CMS + m) * CTX + cbase + c];
        }
        __syncthreads();

        const float* px = &pool[h * (128 * 33) + b * 33];
        const float* pp = &pool[8448 + h * SPER * CMS * 32];
        #pragma unroll 4
        for (int c = 0; c < 32; c++) {
            float x = px[c];
            #pragma unroll
            for (int sl = 0; sl < SPER; sl++)
                #pragma unroll
                for (int m = 0; m < CMS; m++)
                    acc[sl][m] = fmaf(pp[(sl * CMS + m) * 32 + c], x, acc[sl][m]);
        }
        __syncthreads();
    }

    // combine c-halves and emit 6-bit index
    for (int sl = 0; sl < SPER; sl++) {
        if (h == 1) {
            #pragma unroll
            for (int m = 0; m < CMS; m++) pool[b * CMS + m] = acc[sl][m];
        }
        __syncthreads();
        if (h == 0) {
            int idx = 0;
            #pragma unroll
            for (int m = 0; m < CMS; m++) {
                float v = acc[sl][m] + pool[b * CMS + m];
                if (v > pbias[(size_t)(s0 + sl) * CMS + m]) idx |= (1 << m);
            }
            g_ctx[(size_t)(s0 + sl) * BATCH + b] = idx;
        }
        __syncthreads();
    }
}

// ---------------------------------------------------------------------------
// Kernel 3: fused gather-dot / out / update / scatter-copy.
// One block per (slot, neuron). 256 threads, float4 per thread = 1024 floats.
// ---------------------------------------------------------------------------
__global__ __launch_bounds__(256) void main_k(
        const float* __restrict__ weights,
        const float* __restrict__ targets,
        const float* __restrict__ biasp,
        float* __restrict__ out,
        float* __restrict__ neww) {
    const int slot = blockIdx.x;
    const int s    = blockIdx.y;
    const int tid  = threadIdx.x;
    const int lane = tid & 31;
    const int wid  = tid >> 5;

    __shared__ int   s_match[BATCH];
    __shared__ int   s_cnt;
    __shared__ float s_red[8];

    if (tid == 0) s_cnt = 0;
    __syncthreads();
    if (tid < BATCH && g_ctx[(size_t)s * BATCH + tid] == slot) {
        int p = atomicAdd(&s_cnt, 1);
        s_match[p] = tid;
    }

    const size_t rowoff = ((size_t)s * NSLOT + slot) * INPUT;
    float4 w = ((const float4*)(weights + rowoff))[tid];
    __syncthreads();

    const int cnt = s_cnt;
    int bw = -1;
    float ow = 0.0f;
    float4 xw = make_float4(0.f, 0.f, 0.f, 0.f);

    for (int k = 0; k < cnt; k++) {
        if (k) __syncthreads();               // protect s_red reuse
        const int bb = s_match[k];
        float4 x = ((const float4*)(g_logT + (size_t)bb * INPUT))[tid];
        float p = w.x * x.x + w.y * x.y + w.z * x.z + w.w * x.w;
        #pragma unroll
        for (int o = 16; o > 0; o >>= 1)
            p += __shfl_down_sync(0xffffffffu, p, o);
        if (lane == 0) s_red[wid] = p;
        __syncthreads();
        float tot = s_red[0] + s_red[1] + s_red[2] + s_red[3]
                  + s_red[4] + s_red[5] + s_red[6] + s_red[7];
        if (tid == 0)
            out[(size_t)s * BATCH + bb] = (s == 0) ? *biasp : tot;
        if (bb > bw) { bw = bb; ow = tot; xw = x; }   // last-b-wins scatter
    }

    float4 nw = w;
    if (cnt > 0) {
        float o  = (s == 0) ? *biasp : ow;
        float sg = 1.0f / (1.0f + expf(-o));
        sg = fminf(fmaxf(sg, 0.01f), 0.99f);
        float g = 0.01f * (sg - targets[bw]);
        nw.x = fminf(fmaxf(w.x - g * xw.x, -5.0f), 5.0f);
        nw.y = fminf(fmaxf(w.y - g * xw.y, -5.0f), 5.0f);
        nw.z = fminf(fmaxf(w.z - g * xw.z, -5.0f), 5.0f);
        nw.w = fminf(fmaxf(w.w - g * xw.w, -5.0f), 5.0f);
    }
    ((float4*)(neww + rowoff))[tid] = nw;
}

// ---------------------------------------------------------------------------
extern "C" void kernel_launch(void* const* d_in, const int* in_sizes, int n_in,
                              void* d_out, int out_size) {
    const float* logits  = (const float*)d_in[0];  // (1024, 128)
    const float* ctxin   = (const float*)d_in[1];  // (512, 128)
    const float* targets = (const float*)d_in[2];  // (128,)
    const float* proj    = (const float*)d_in[3];  // (1024, 6, 512)
    const float* pbias   = (const float*)d_in[4];  // (1024, 6, 1)
    const float* weights = (const float*)d_in[5];  // (1024, 64, 1024)
    const float* biasp   = (const float*)d_in[6];  // ()

    float* out  = (float*)d_out;                   // (1024, 128)
    float* neww = out + (size_t)SIZE * BATCH;      // (1024, 64, 1024)

    dim3 tb(32, 8), tg(INPUT / 32, BATCH / 32);
    transpose_logits_k<<<tg, tb>>>(logits);
    ctx_k<<<SIZE / SPER, 256>>>(proj, pbias, ctxin);
    main_k<<<dim3(NSLOT, SIZE), 256>>>(weights, targets, biasp, out, neww);
}

// round 2
// speedup vs baseline: 1.3090x; 1.3090x over previous
#include <cuda_runtime.h>
#include <math.h>

#define SIZE   1024
#define INPUT  1024
#define CTX    512
#define CMS    6
#define NSLOT  64
#define BATCH  128
#define SPER   8      // neurons per block in ctx kernel

// Scratch (device globals — no allocation allowed)
__device__ float g_logT[BATCH * INPUT];   // logits transposed: [b][i]
__device__ int   g_ctx [SIZE * BATCH];    // context index:     [s][b]

// ---------------------------------------------------------------------------
// Kernel 1: transpose logits (INPUT, BATCH) -> (BATCH, INPUT) for coalesced dots
// ---------------------------------------------------------------------------
__global__ void transpose_logits_k(const float* __restrict__ in) {
    __shared__ float tile[32][33];
    int i0 = blockIdx.x * 32;
    int b0 = blockIdx.y * 32;
    int x = threadIdx.x, y = threadIdx.y;
    #pragma unroll
    for (int j = 0; j < 32; j += 8)
        tile[y + j][x] = in[(size_t)(i0 + y + j) * BATCH + (b0 + x)];
    __syncthreads();
    #pragma unroll
    for (int j = 0; j < 32; j += 8)
        g_logT[(size_t)(b0 + y + j) * INPUT + (i0 + x)] = tile[x][y + j];
}

// ---------------------------------------------------------------------------
// Kernel 2: context hashing.
// projected[s,m,b] = sum_c proj[s,m,c] * ctx[c,b];  bit m = projected > pbias[s,m]
// ---------------------------------------------------------------------------
__global__ __launch_bounds__(256) void ctx_k(
        const float* __restrict__ proj,
        const float* __restrict__ pbias,
        const float* __restrict__ ctxin) {
    __shared__ float pool[11520];
    const int tid = threadIdx.x;
    const int b = tid & 127;
    const int h = tid >> 7;
    const int s0 = blockIdx.x * SPER;

    float acc[SPER][CMS];
    #pragma unroll
    for (int sl = 0; sl < SPER; sl++)
        #pragma unroll
        for (int m = 0; m < CMS; m++) acc[sl][m] = 0.0f;

    for (int r = 0; r < 8; r++) {
        const int cbase = h * 256 + r * 32;
        #pragma unroll 4
        for (int c = 0; c < 32; c++)
            pool[h * (128 * 33) + b * 33 + c] =
                ctxin[(size_t)(cbase + c) * BATCH + b];
        for (int l = b; l < SPER * CMS * 32; l += 128) {
            int sl = l / (CMS * 32);
            int m  = (l / 32) % CMS;
            int c  = l & 31;
            pool[8448 + ((h * SPER + sl) * CMS + m) * 32 + c] =
                proj[((size_t)(s0 + sl) * CMS + m) * CTX + cbase + c];
        }
        __syncthreads();

        const float* px = &pool[h * (128 * 33) + b * 33];
        const float* pp = &pool[8448 + h * SPER * CMS * 32];
        #pragma unroll 4
        for (int c = 0; c < 32; c++) {
            float x = px[c];
            #pragma unroll
            for (int sl = 0; sl < SPER; sl++)
                #pragma unroll
                for (int m = 0; m < CMS; m++)
                    acc[sl][m] = fmaf(pp[(sl * CMS + m) * 32 + c], x, acc[sl][m]);
        }
        __syncthreads();
    }

    for (int sl = 0; sl < SPER; sl++) {
        if (h == 1) {
            #pragma unroll
            for (int m = 0; m < CMS; m++) pool[b * CMS + m] = acc[sl][m];
        }
        __syncthreads();
        if (h == 0) {
            int idx = 0;
            #pragma unroll
            for (int m = 0; m < CMS; m++) {
                float v = acc[sl][m] + pool[b * CMS + m];
                if (v > pbias[(size_t)(s0 + sl) * CMS + m]) idx |= (1 << m);
            }
            g_ctx[(size_t)(s0 + sl) * BATCH + b] = idx;
        }
        __syncthreads();
    }
}

// ---------------------------------------------------------------------------
// Kernel 3: warp-per-row fused gather-dot / out / update / scatter-copy.
// grid = (8, SIZE): block (g, s) handles slots [g*8, g*8+8) of neuron s,
// one warp per slot. Consecutive blocks stream contiguous 32KB row ranges.
// No block barriers after the ctx-row smem load; dots are warp-local.
// ---------------------------------------------------------------------------
__global__ __launch_bounds__(256) void main_k(
        const float* __restrict__ weights,
        const float* __restrict__ targets,
        const float* __restrict__ biasp,
        float* __restrict__ out,
        float* __restrict__ neww) {
    const int s    = blockIdx.y;
    const int tid  = threadIdx.x;
    const int lane = tid & 31;
    const int wid  = tid >> 5;
    const int slot = blockIdx.x * 8 + wid;

    __shared__ int s_ctx[BATCH];
    if (tid < BATCH) s_ctx[tid] = g_ctx[(size_t)s * BATCH + tid];

    // load this warp's weight row into registers (8 float4 per lane, coalesced)
    const size_t rowoff = ((size_t)s * NSLOT + slot) * INPUT;
    const float4* wrow = (const float4*)(weights + rowoff);
    float4 w[8];
    #pragma unroll
    for (int k = 0; k < 8; k++) w[k] = wrow[k * 32 + lane];

    __syncthreads();

    int   last    = -1;
    float lasttot = 0.0f;

    #pragma unroll
    for (int j = 0; j < 4; j++) {
        const int bb0 = j * 32;
        const int v = s_ctx[bb0 + lane];
        unsigned m = __ballot_sync(0xffffffffu, v == slot);
        while (m) {
            const int bit = __ffs(m) - 1;
            m &= m - 1;
            const int bb = bb0 + bit;
            const float4* xr = (const float4*)(g_logT + (size_t)bb * INPUT);
            float acc = 0.0f;
            #pragma unroll
            for (int k = 0; k < 8; k++) {
                float4 x = xr[k * 32 + lane];
                acc += w[k].x * x.x + w[k].y * x.y + w[k].z * x.z + w[k].w * x.w;
            }
            #pragma unroll
            for (int o = 16; o > 0; o >>= 1)
                acc += __shfl_xor_sync(0xffffffffu, acc, o);
            if (lane == 0)
                out[(size_t)s * BATCH + bb] = (s == 0) ? *biasp : acc;
            last = bb;            // ascending scan -> ends at max b (last-wins)
            lasttot = acc;
        }
    }

    if (last >= 0) {
        float o  = (s == 0) ? *biasp : lasttot;
        float sg = 1.0f / (1.0f + expf(-o));
        sg = fminf(fmaxf(sg, 0.01f), 0.99f);
        const float g = 0.01f * (sg - __ldg(&targets[last]));
        const float4* xr = (const float4*)(g_logT + (size_t)last * INPUT);
        #pragma unroll
        for (int k = 0; k < 8; k++) {
            float4 x = xr[k * 32 + lane];
            w[k].x = fminf(fmaxf(w[k].x - g * x.x, -5.0f), 5.0f);
            w[k].y = fminf(fmaxf(w[k].y - g * x.y, -5.0f), 5.0f);
            w[k].z = fminf(fmaxf(w[k].z - g * x.z, -5.0f), 5.0f);
            w[k].w = fminf(fmaxf(w[k].w - g * x.w, -5.0f), 5.0f);
        }
    }

    float4* orow = (float4*)(neww + rowoff);
    #pragma unroll
    for (int k = 0; k < 8; k++) orow[k * 32 + lane] = w[k];
}

// ---------------------------------------------------------------------------
extern "C" void kernel_launch(void* const* d_in, const int* in_sizes, int n_in,
                              void* d_out, int out_size) {
    const float* logits  = (const float*)d_in[0];  // (1024, 128)
    const float* ctxin   = (const float*)d_in[1];  // (512, 128)
    const float* targets = (const float*)d_in[2];  // (128,)
    const float* proj    = (const float*)d_in[3];  // (1024, 6, 512)
    const float* pbias   = (const float*)d_in[4];  // (1024, 6, 1)
    const float* weights = (const float*)d_in[5];  // (1024, 64, 1024)
    const float* biasp   = (const float*)d_in[6];  // ()

    float* out  = (float*)d_out;                   // (1024, 128)
    float* neww = out + (size_t)SIZE * BATCH;      // (1024, 64, 1024)

    dim3 tb(32, 8), tg(INPUT / 32, BATCH / 32);
    transpose_logits_k<<<tg, tb>>>(logits);
    ctx_k<<<SIZE / SPER, 256>>>(proj, pbias, ctxin);
    main_k<<<dim3(NSLOT / 8, SIZE), 256>>>(weights, targets, biasp, out, neww);
}

// round 3
// speedup vs baseline: 1.4855x; 1.1348x over previous
#include <cuda_runtime.h>
#include <math.h>

#define SIZE   1024
#define INPUT  1024
#define CTX    512
#define CMS    6
#define NSLOT  64
#define BATCH  128
#define SPER   8      // neurons per block in ctx kernel
#define CPAD   34     // ctx tile row pad (even -> 8B-aligned LDS.64)
#define PBASE  (2 * 128 * CPAD)   // 8704 floats

// Scratch (device globals — no allocation allowed)
__device__ float g_logT[BATCH * INPUT];   // logits transposed: [b][i]
__device__ int   g_ctx [SIZE * BATCH];    // context index:     [s][b]

__device__ __forceinline__ void fma2(unsigned long long& d,
                                     unsigned long long a,
                                     unsigned long long b) {
    asm("fma.rn.f32x2 %0, %1, %2, %3;" : "=l"(d) : "l"(a), "l"(b), "l"(d));
}

// ---------------------------------------------------------------------------
// Kernel 1: context hashing (f32x2 packed) + folded logits transpose.
// projected[s,m,b] = sum_c proj[s,m,c] * ctx[c,b];  bit m = projected > pbias
// Block = SPER neurons; 256 threads = (b in [0,128)) x (h in {0,1} c-halves).
// Also transposes 8 logits rows per block (hides under issue-bound compute).
// ---------------------------------------------------------------------------
__global__ __launch_bounds__(256) void ctx_k(
        const float* __restrict__ proj,
        const float* __restrict__ pbias,
        const float* __restrict__ ctxin,
        const float* __restrict__ logits) {
    __shared__ float pool[PBASE + 2 * SPER * CMS * 32];   // 11776 floats
    const int tid = threadIdx.x;
    const int b = tid & 127;
    const int h = tid >> 7;
    const int s0 = blockIdx.x * SPER;

    // folded transpose: this block moves logits rows [8*bx, 8*bx+8)
    {
        const int i0 = blockIdx.x * 8;
        #pragma unroll
        for (int l = tid; l < 8 * 128; l += 256) {
            const int i = l >> 7, bb = l & 127;
            g_logT[(size_t)bb * INPUT + (i0 + i)] =
                logits[(size_t)(i0 + i) * BATCH + bb];
        }
    }

    unsigned long long acc2[SPER][CMS];
    #pragma unroll
    for (int sl = 0; sl < SPER; sl++)
        #pragma unroll
        for (int m = 0; m < CMS; m++) acc2[sl][m] = 0ull;

    for (int r = 0; r < 8; r++) {
        const int cbase = h * 256 + r * 32;
        #pragma unroll 4
        for (int c = 0; c < 32; c++)
            pool[h * (128 * CPAD) + b * CPAD + c] =
                ctxin[(size_t)(cbase + c) * BATCH + b];
        for (int l = b; l < SPER * CMS * 32; l += 128) {
            int sl = l / (CMS * 32);
            int m  = (l / 32) % CMS;
            int c  = l & 31;
            pool[PBASE + ((h * SPER + sl) * CMS + m) * 32 + c] =
                proj[((size_t)(s0 + sl) * CMS + m) * CTX + cbase + c];
        }
        __syncthreads();

        const float* px = &pool[h * (128 * CPAD) + b * CPAD];
        const float* pp = &pool[PBASE + h * SPER * CMS * 32];
        #pragma unroll 2
        for (int c = 0; c < 32; c += 2) {
            const unsigned long long x2 =
                *(const unsigned long long*)(px + c);
            #pragma unroll
            for (int sl = 0; sl < SPER; sl++)
                #pragma unroll
                for (int m = 0; m < CMS; m++) {
                    const unsigned long long p2 =
                        *(const unsigned long long*)(pp + (sl * CMS + m) * 32 + c);
                    fma2(acc2[sl][m], p2, x2);
                }
        }
        __syncthreads();
    }

    // combine f32x2 halves + c-halves, emit 6-bit index
    for (int sl = 0; sl < SPER; sl++) {
        float s[CMS];
        #pragma unroll
        for (int m = 0; m < CMS; m++) {
            union { unsigned long long u; float2 f; } cv;
            cv.u = acc2[sl][m];
            s[m] = cv.f.x + cv.f.y;
        }
        if (h == 1) {
            #pragma unroll
            for (int m = 0; m < CMS; m++) pool[b * CMS + m] = s[m];
        }
        __syncthreads();
        if (h == 0) {
            int idx = 0;
            #pragma unroll
            for (int m = 0; m < CMS; m++) {
                float v = s[m] + pool[b * CMS + m];
                if (v > pbias[(size_t)(s0 + sl) * CMS + m]) idx |= (1 << m);
            }
            g_ctx[(size_t)(s0 + sl) * BATCH + b] = idx;
        }
        __syncthreads();
    }
}

// ---------------------------------------------------------------------------
// Kernel 2: warp-per-row fused gather-dot / out / update / scatter-copy.
// Streaming traffic (weights in, new_weights out) uses evict-first hints so
// the hot 512KB g_logT stays L2-resident.
// ---------------------------------------------------------------------------
__global__ __launch_bounds__(256) void main_k(
        const float* __restrict__ weights,
        const float* __restrict__ targets,
        const float* __restrict__ biasp,
        float* __restrict__ out,
        float* __restrict__ neww) {
    const int s    = blockIdx.y;
    const int tid  = threadIdx.x;
    const int lane = tid & 31;
    const int wid  = tid >> 5;
    const int slot = blockIdx.x * 8 + wid;

    __shared__ int s_ctx[BATCH];
    if (tid < BATCH) s_ctx[tid] = g_ctx[(size_t)s * BATCH + tid];

    // load this warp's weight row into registers (evict-first: read-once)
    const size_t rowoff = ((size_t)s * NSLOT + slot) * INPUT;
    const float4* wrow = (const float4*)(weights + rowoff);
    float4 w[8];
    #pragma unroll
    for (int k = 0; k < 8; k++) w[k] = __ldcs(wrow + k * 32 + lane);

    __syncthreads();

    int   last    = -1;
    float lasttot = 0.0f;

    #pragma unroll
    for (int j = 0; j < 4; j++) {
        const int bb0 = j * 32;
        const int v = s_ctx[bb0 + lane];
        unsigned m = __ballot_sync(0xffffffffu, v == slot);
        while (m) {
            const int bit = __ffs(m) - 1;
            m &= m - 1;
            const int bb = bb0 + bit;
            const float4* xr = (const float4*)(g_logT + (size_t)bb * INPUT);
            float acc = 0.0f;
            #pragma unroll
            for (int k = 0; k < 8; k++) {
                float4 x = __ldg(xr + k * 32 + lane);
                acc += w[k].x * x.x + w[k].y * x.y + w[k].z * x.z + w[k].w * x.w;
            }
            #pragma unroll
            for (int o = 16; o > 0; o >>= 1)
                acc += __shfl_xor_sync(0xffffffffu, acc, o);
            if (lane == 0)
                out[(size_t)s * BATCH + bb] = (s == 0) ? *biasp : acc;
            last = bb;            // ascending scan -> ends at max b (last-wins)
            lasttot = acc;
        }
    }

    if (last >= 0) {
        float o  = (s == 0) ? *biasp : lasttot;
        float sg = 1.0f / (1.0f + expf(-o));
        sg = fminf(fmaxf(sg, 0.01f), 0.99f);
        const float g = 0.01f * (sg - __ldg(&targets[last]));
        const float4* xr = (const float4*)(g_logT + (size_t)last * INPUT);
        #pragma unroll
        for (int k = 0; k < 8; k++) {
            float4 x = __ldg(xr + k * 32 + lane);
            w[k].x = fminf(fmaxf(w[k].x - g * x.x, -5.0f), 5.0f);
            w[k].y = fminf(fmaxf(w[k].y - g * x.y, -5.0f), 5.0f);
            w[k].z = fminf(fmaxf(w[k].z - g * x.z, -5.0f), 5.0f);
            w[k].w = fminf(fmaxf(w[k].w - g * x.w, -5.0f), 5.0f);
        }
    }

    float4* orow = (float4*)(neww + rowoff);
    #pragma unroll
    for (int k = 0; k < 8; k++) __stcs(orow + k * 32 + lane, w[k]);
}

// ---------------------------------------------------------------------------
extern "C" void kernel_launch(void* const* d_in, const int* in_sizes, int n_in,
                              void* d_out, int out_size) {
    const float* logits  = (const float*)d_in[0];  // (1024, 128)
    const float* ctxin   = (const float*)d_in[1];  // (512, 128)
    const float* targets = (const float*)d_in[2];  // (128,)
    const float* proj    = (const float*)d_in[3];  // (1024, 6, 512)
    const float* pbias   = (const float*)d_in[4];  // (1024, 6, 1)
    const float* weights = (const float*)d_in[5];  // (1024, 64, 1024)
    const float* biasp   = (const float*)d_in[6];  // ()

    float* out  = (float*)d_out;                   // (1024, 128)
    float* neww = out + (size_t)SIZE * BATCH;      // (1024, 64, 1024)

    ctx_k<<<SIZE / SPER, 256>>>(proj, pbias, ctxin, logits);
    main_k<<<dim3(NSLOT / 8, SIZE), 256>>>(weights, targets, biasp, out, neww);
}

// round 4
// speedup vs baseline: 1.7577x; 1.1833x over previous
#include <cuda_runtime.h>
#include <math.h>

#define SIZE   1024
#define INPUT  1024
#define CTX    512
#define CMS    6
#define NSLOT  64
#define BATCH  128
#define SPER   8      // neurons per block in ctx kernel
#define KBLK   32

// Scratch (device globals — no allocation allowed)
__device__ float g_logT[BATCH * INPUT];   // logits transposed: [b][i]
__device__ int   g_ctx [SIZE * BATCH];    // context index:     [s][b]

__device__ __forceinline__ void fma2(unsigned long long& d,
                                     unsigned long long a,
                                     unsigned long long b) {
    asm("fma.rn.f32x2 %0, %1, %2, %3;" : "=l"(d) : "l"(a), "l"(b), "l"(d));
}
__device__ __forceinline__ unsigned long long dup2(float x) {
    unsigned long long r;
    asm("mov.b64 %0, {%1, %1};" : "=l"(r) : "f"(x));
    return r;
}

// ---------------------------------------------------------------------------
// Kernel 1: context hashing, register-tiled GEMM (48 rows x 128 b per block).
// warp = one neuron sl; lane = b-quad (4 b). Thread computes all 6 m for its
// 4 b over full K=512 -> no cross-thread reduction. Accum = 3 m-pairs x 4 b
// as f32x2 (24 regs). Also transposes 8 logits rows per block via smem tile.
// ---------------------------------------------------------------------------
__global__ __launch_bounds__(256) void ctx_k(
        const float* __restrict__ proj,
        const float* __restrict__ pbias,
        const float* __restrict__ ctxin,
        const float* __restrict__ logits) {
    __shared__ float s_x[KBLK][BATCH];              // 16KB ctx tile
    __shared__ float s_p[SPER][KBLK][CMS];          // 6KB  proj tile [sl][c][m]
    const int tid = threadIdx.x;
    const int sl  = tid >> 5;          // warp id = neuron within group
    const int bq  = tid & 31;          // b-quad: b = bq*4 .. bq*4+3
    const int s0  = blockIdx.x * SPER;

    // --- folded logits transpose: rows [8*bx, 8*bx+8) through smem tile ---
    {
        const int i0 = blockIdx.x * 8;
        float* flat = &s_x[0][0];
        #pragma unroll
        for (int l = tid; l < 1024; l += 256)
            flat[l] = logits[(size_t)(i0 + (l >> 7)) * BATCH + (l & 127)];
        __syncthreads();
        #pragma unroll
        for (int l = tid; l < 1024; l += 256) {
            const int b = l >> 3, i = l & 7;
            g_logT[(size_t)b * INPUT + i0 + i] = flat[i * 128 + b];
        }
        __syncthreads();
    }

    unsigned long long acc[3][4];      // [m-pair][b-in-quad] = (sum_m0,sum_m1)
    #pragma unroll
    for (int jp = 0; jp < 3; jp++)
        #pragma unroll
        for (int j = 0; j < 4; j++) acc[jp][j] = 0ull;

    for (int kb = 0; kb < CTX; kb += KBLK) {
        // ctx tile: 4096 floats, coalesced (lane = b)
        #pragma unroll
        for (int l = tid; l < KBLK * BATCH; l += 256)
            s_x[l >> 7][l & 127] = ctxin[(size_t)(kb + (l >> 7)) * BATCH + (l & 127)];
        // proj tile: 48 rows x 32 c, gmem-coalesced, smem scattered [sl][c][m]
        #pragma unroll
        for (int l = tid; l < SPER * CMS * KBLK; l += 256) {
            const int row = l >> 5;            // sl*CMS + m
            const int c   = l & 31;
            s_p[row / CMS][c][row % CMS] =
                proj[((size_t)s0 * CMS + row) * CTX + kb + c];
        }
        __syncthreads();

        #pragma unroll 8
        for (int c = 0; c < KBLK; c++) {
            const float4 xv = *(const float4*)&s_x[c][bq * 4];
            const unsigned long long xb[4] = {
                dup2(xv.x), dup2(xv.y), dup2(xv.z), dup2(xv.w) };
            #pragma unroll
            for (int jp = 0; jp < 3; jp++) {
                const unsigned long long p2 =
                    *(const unsigned long long*)&s_p[sl][c][2 * jp];
                fma2(acc[jp][0], p2, xb[0]);
                fma2(acc[jp][1], p2, xb[1]);
                fma2(acc[jp][2], p2, xb[2]);
                fma2(acc[jp][3], p2, xb[3]);
            }
        }
        __syncthreads();
    }

    // threshold + 6-bit index for this thread's 4 b values
    float pb[CMS];
    #pragma unroll
    for (int m = 0; m < CMS; m++)
        pb[m] = pbias[(size_t)(s0 + sl) * CMS + m];

    int4 idx4;
    int* idxp = (int*)&idx4;
    #pragma unroll
    for (int j = 0; j < 4; j++) {
        int idx = 0;
        #pragma unroll
        for (int jp = 0; jp < 3; jp++) {
            union { unsigned long long u; float2 f; } cv;
            cv.u = acc[jp][j];
            if (cv.f.x > pb[2 * jp])     idx |= (1 << (2 * jp));
            if (cv.f.y > pb[2 * jp + 1]) idx |= (1 << (2 * jp + 1));
        }
        idxp[j] = idx;
    }
    *(int4*)&g_ctx[(size_t)(s0 + sl) * BATCH + bq * 4] = idx4;
}

// ---------------------------------------------------------------------------
// Kernel 2: warp-per-row fused gather-dot / out / update / scatter-copy.
// Streaming traffic evict-first; 4 blocks/SM for more DRAM-level parallelism.
// ---------------------------------------------------------------------------
__global__ __launch_bounds__(256, 4) void main_k(
        const float* __restrict__ weights,
        const float* __restrict__ targets,
        const float* __restrict__ biasp,
        float* __restrict__ out,
        float* __restrict__ neww) {
    const int s    = blockIdx.y;
    const int tid  = threadIdx.x;
    const int lane = tid & 31;
    const int wid  = tid >> 5;
    const int slot = blockIdx.x * 8 + wid;

    __shared__ int s_ctx[BATCH];
    if (tid < BATCH) s_ctx[tid] = g_ctx[(size_t)s * BATCH + tid];

    const size_t rowoff = ((size_t)s * NSLOT + slot) * INPUT;
    const float4* wrow = (const float4*)(weights + rowoff);
    float4 w[8];
    #pragma unroll
    for (int k = 0; k < 8; k++) w[k] = __ldcs(wrow + k * 32 + lane);

    __syncthreads();

    int   last    = -1;
    float lasttot = 0.0f;

    #pragma unroll
    for (int j = 0; j < 4; j++) {
        const int bb0 = j * 32;
        const int v = s_ctx[bb0 + lane];
        unsigned m = __ballot_sync(0xffffffffu, v == slot);
        while (m) {
            const int bit = __ffs(m) - 1;
            m &= m - 1;
            const int bb = bb0 + bit;
            const float4* xr = (const float4*)(g_logT + (size_t)bb * INPUT);
            float acc = 0.0f;
            #pragma unroll
            for (int k = 0; k < 8; k++) {
                float4 x = __ldg(xr + k * 32 + lane);
                acc += w[k].x * x.x + w[k].y * x.y + w[k].z * x.z + w[k].w * x.w;
            }
            #pragma unroll
            for (int o = 16; o > 0; o >>= 1)
                acc += __shfl_xor_sync(0xffffffffu, acc, o);
            if (lane == 0)
                out[(size_t)s * BATCH + bb] = (s == 0) ? *biasp : acc;
            last = bb;            // ascending scan -> ends at max b (last-wins)
            lasttot = acc;
        }
    }

    if (last >= 0) {
        float o  = (s == 0) ? *biasp : lasttot;
        float sg = 1.0f / (1.0f + expf(-o));
        sg = fminf(fmaxf(sg, 0.01f), 0.99f);
        const float g = 0.01f * (sg - __ldg(&targets[last]));
        const float4* xr = (const float4*)(g_logT + (size_t)last * INPUT);
        #pragma unroll
        for (int k = 0; k < 8; k++) {
            float4 x = __ldg(xr + k * 32 + lane);
            w[k].x = fminf(fmaxf(w[k].x - g * x.x, -5.0f), 5.0f);
            w[k].y = fminf(fmaxf(w[k].y - g * x.y, -5.0f), 5.0f);
            w[k].z = fminf(fmaxf(w[k].z - g * x.z, -5.0f), 5.0f);
            w[k].w = fminf(fmaxf(w[k].w - g * x.w, -5.0f), 5.0f);
        }
    }

    float4* orow = (float4*)(neww + rowoff);
    #pragma unroll
    for (int k = 0; k < 8; k++) __stcs(orow + k * 32 + lane, w[k]);
}

// ---------------------------------------------------------------------------
extern "C" void kernel_launch(void* const* d_in, const int* in_sizes, int n_in,
                              void* d_out, int out_size) {
    const float* logits  = (const float*)d_in[0];  // (1024, 128)
    const float* ctxin   = (const float*)d_in[1];  // (512, 128)
    const float* targets = (const float*)d_in[2];  // (128,)
    const float* proj    = (const float*)d_in[3];  // (1024, 6, 512)
    const float* pbias   = (const float*)d_in[4];  // (1024, 6, 1)
    const float* weights = (const float*)d_in[5];  // (1024, 64, 1024)
    const float* biasp   = (const float*)d_in[6];  // ()

    float* out  = (float*)d_out;                   // (1024, 128)
    float* neww = out + (size_t)SIZE * BATCH;      // (1024, 64, 1024)

    ctx_k<<<SIZE / SPER, 256>>>(proj, pbias, ctxin, logits);
    main_k<<<dim3(NSLOT / 8, SIZE), 256>>>(weights, targets, biasp, out, neww);
}

// round 5
// speedup vs baseline: 1.9230x; 1.0940x over previous
#include <cuda_runtime.h>
#include <math.h>

#define SIZE   1024
#define INPUT  1024
#define CTX    512
#define CMS    6
#define NSLOT  64
#define BATCH  128
#define SPER   8      // neurons per block in ctx kernel
#define KBLK   32
#define KHALF  (CTX / 2)

// Scratch (device globals — no allocation allowed)
__device__ float g_logT[BATCH * INPUT];   // logits transposed: [b][i]
__device__ int   g_ctx [SIZE * BATCH];    // context index:     [s][b]

__device__ __forceinline__ void fma2(unsigned long long& d,
                                     unsigned long long a,
                                     unsigned long long b) {
    asm("fma.rn.f32x2 %0, %1, %2, %3;" : "=l"(d) : "l"(a), "l"(b), "l"(d));
}
__device__ __forceinline__ unsigned long long dup2(float x) {
    unsigned long long r;
    asm("mov.b64 %0, {%1, %1};" : "=l"(r) : "f"(x));
    return r;
}

// ---------------------------------------------------------------------------
// Kernel 1: context hashing, register-tiled GEMM, K split across warp pairs.
// 512 threads = 16 warps: warp w -> neuron sl = w>>1, K-half = w&1 (256 c).
// Thread tile: 6 m x 4 b as 3 f32x2-pairs x 4 (24 accumulator regs).
// Partial K-sums combined via smem; half-0 warps threshold + emit indices.
// Also transposes 8 logits rows per block (folded, via smem staging).
// ---------------------------------------------------------------------------
__global__ __launch_bounds__(512) void ctx_k(
        const float* __restrict__ proj,
        const float* __restrict__ pbias,
        const float* __restrict__ ctxin,
        const float* __restrict__ logits) {
    __shared__ float  s_x[2][KBLK][BATCH];           // 32KB ctx tiles (per half)
    __shared__ float  s_p[2][SPER][KBLK][CMS];       // 12KB proj tiles [h][sl][c][m]
    __shared__ float2 s_red[SPER][32][12];           // 24KB partial sums
    const int tid  = threadIdx.x;
    const int wid  = tid >> 5;
    const int lane = tid & 31;
    const int sl   = wid >> 1;          // neuron within group
    const int half = wid & 1;           // K-half
    const int s0   = blockIdx.x * SPER;

    // --- folded logits transpose: rows [8*bx, 8*bx+8) via smem staging ---
    {
        const int i0 = blockIdx.x * 8;
        float* flat = &s_x[0][0][0];
        #pragma unroll
        for (int l = tid; l < 1024; l += 512)
            flat[l] = logits[(size_t)(i0 + (l >> 7)) * BATCH + (l & 127)];
        __syncthreads();
        #pragma unroll
        for (int l = tid; l < 1024; l += 512) {
            const int b = l >> 3, i = l & 7;
            g_logT[(size_t)b * INPUT + i0 + i] = flat[i * 128 + b];
        }
        __syncthreads();
    }

    unsigned long long acc[3][4];       // [m-pair][b-in-quad]
    #pragma unroll
    for (int jp = 0; jp < 3; jp++)
        #pragma unroll
        for (int j = 0; j < 4; j++) acc[jp][j] = 0ull;

    for (int kb = 0; kb < KHALF; kb += KBLK) {
        // ctx tiles: 8192 floats, coalesced (inner index = b)
        #pragma unroll
        for (int l = tid; l < 2 * KBLK * BATCH; l += 512) {
            const int h = l >> 12;
            const int r = l & 4095;
            const int c = r >> 7, b = r & 127;
            s_x[h][c][b] = ctxin[(size_t)(h * KHALF + kb + c) * BATCH + b];
        }
        // proj tiles: 3072 floats, gmem-coalesced over c
        #pragma unroll
        for (int l = tid; l < 2 * SPER * CMS * KBLK; l += 512) {
            const int h   = l / (SPER * CMS * KBLK);
            const int r   = l % (SPER * CMS * KBLK);
            const int row = r >> 5;                    // sl*CMS + m
            const int c   = r & 31;
            s_p[h][row / CMS][c][row % CMS] =
                proj[((size_t)(s0 + row / CMS) * CMS + (row % CMS)) * CTX
                     + h * KHALF + kb + c];
        }
        __syncthreads();

        const float (*px)[BATCH] = s_x[half];
        const float (*pp)[CMS]   = s_p[half][sl];
        #pragma unroll 8
        for (int c = 0; c < KBLK; c++) {
            const float4 xv = *(const float4*)&px[c][lane * 4];
            const unsigned long long xb[4] = {
                dup2(xv.x), dup2(xv.y), dup2(xv.z), dup2(xv.w) };
            #pragma unroll
            for (int jp = 0; jp < 3; jp++) {
                const unsigned long long p2 =
                    *(const unsigned long long*)&pp[c][2 * jp];
                fma2(acc[jp][0], p2, xb[0]);
                fma2(acc[jp][1], p2, xb[1]);
                fma2(acc[jp][2], p2, xb[2]);
                fma2(acc[jp][3], p2, xb[3]);
            }
        }
        __syncthreads();
    }

    // combine K-halves: half-1 publishes, half-0 adds + thresholds
    if (half == 1) {
        #pragma unroll
        for (int jp = 0; jp < 3; jp++)
            #pragma unroll
            for (int j = 0; j < 4; j++) {
                union { unsigned long long u; float2 f; } cv;
                cv.u = acc[jp][j];
                s_red[sl][lane][jp * 4 + j] = cv.f;
            }
    }
    __syncthreads();
    if (half == 0) {
        float pb[CMS];
        #pragma unroll
        for (int m = 0; m < CMS; m++)
            pb[m] = pbias[(size_t)(s0 + sl) * CMS + m];

        int4 idx4;
        int* idxp = (int*)&idx4;
        #pragma unroll
        for (int j = 0; j < 4; j++) {
            int idx = 0;
            #pragma unroll
            for (int jp = 0; jp < 3; jp++) {
                union { unsigned long long u; float2 f; } cv;
                cv.u = acc[jp][j];
                const float2 o = s_red[sl][lane][jp * 4 + j];
                if (cv.f.x + o.x > pb[2 * jp])     idx |= (1 << (2 * jp));
                if (cv.f.y + o.y > pb[2 * jp + 1]) idx |= (1 << (2 * jp + 1));
            }
            idxp[j] = idx;
        }
        *(int4*)&g_ctx[(size_t)(s0 + sl) * BATCH + lane * 4] = idx4;
    }
}

// ---------------------------------------------------------------------------
// Kernel 2: warp-per-row fused gather-dot / out / update / scatter-copy.
// Streaming traffic evict-first so the hot 512KB g_logT stays L2-resident.
// ---------------------------------------------------------------------------
__global__ __launch_bounds__(256, 4) void main_k(
        const float* __restrict__ weights,
        const float* __restrict__ targets,
        const float* __restrict__ biasp,
        float* __restrict__ out,
        float* __restrict__ neww) {
    const int s    = blockIdx.y;
    const int tid  = threadIdx.x;
    const int lane = tid & 31;
    const int wid  = tid >> 5;
    const int slot = blockIdx.x * 8 + wid;

    __shared__ int s_ctx[BATCH];
    if (tid < BATCH) s_ctx[tid] = g_ctx[(size_t)s * BATCH + tid];

    const size_t rowoff = ((size_t)s * NSLOT + slot) * INPUT;
    const float4* wrow = (const float4*)(weights + rowoff);
    float4 w[8];
    #pragma unroll
    for (int k = 0; k < 8; k++) w[k] = __ldcs(wrow + k * 32 + lane);

    __syncthreads();

    int   last    = -1;
    float lasttot = 0.0f;

    #pragma unroll
    for (int j = 0; j < 4; j++) {
        const int bb0 = j * 32;
        const int v = s_ctx[bb0 + lane];
        unsigned m = __ballot_sync(0xffffffffu, v == slot);
        while (m) {
            const int bit = __ffs(m) - 1;
            m &= m - 1;
            const int bb = bb0 + bit;
            const float4* xr = (const float4*)(g_logT + (size_t)bb * INPUT);
            float acc = 0.0f;
            #pragma unroll
            for (int k = 0; k < 8; k++) {
                float4 x = __ldg(xr + k * 32 + lane);
                acc += w[k].x * x.x + w[k].y * x.y + w[k].z * x.z + w[k].w * x.w;
            }
            #pragma unroll
            for (int o = 16; o > 0; o >>= 1)
                acc += __shfl_xor_sync(0xffffffffu, acc, o);
            if (lane == 0)
                out[(size_t)s * BATCH + bb] = (s == 0) ? *biasp : acc;
            last = bb;            // ascending scan -> ends at max b (last-wins)
            lasttot = acc;
        }
    }

    if (last >= 0) {
        float o  = (s == 0) ? *biasp : lasttot;
        float sg = 1.0f / (1.0f + expf(-o));
        sg = fminf(fmaxf(sg, 0.01f), 0.99f);
        const float g = 0.01f * (sg - __ldg(&targets[last]));
        const float4* xr = (const float4*)(g_logT + (size_t)last * INPUT);
        #pragma unroll
        for (int k = 0; k < 8; k++) {
            float4 x = __ldg(xr + k * 32 + lane);
            w[k].x = fminf(fmaxf(w[k].x - g * x.x, -5.0f), 5.0f);
            w[k].y = fminf(fmaxf(w[k].y - g * x.y, -5.0f), 5.0f);
            w[k].z = fminf(fmaxf(w[k].z - g * x.z, -5.0f), 5.0f);
            w[k].w = fminf(fmaxf(w[k].w - g * x.w, -5.0f), 5.0f);
        }
    }

    float4* orow = (float4*)(neww + rowoff);
    #pragma unroll
    for (int k = 0; k < 8; k++) __stcs(orow + k * 32 + lane, w[k]);
}

// ---------------------------------------------------------------------------
extern "C" void kernel_launch(void* const* d_in, const int* in_sizes, int n_in,
                              void* d_out, int out_size) {
    const float* logits  = (const float*)d_in[0];  // (1024, 128)
    const float* ctxin   = (const float*)d_in[1];  // (512, 128)
    const float* targets = (const float*)d_in[2];  // (128,)
    const float* proj    = (const float*)d_in[3];  // (1024, 6, 512)
    const float* pbias   = (const float*)d_in[4];  // (1024, 6, 1)
    const float* weights = (const float*)d_in[5];  // (1024, 64, 1024)
    const float* biasp   = (const float*)d_in[6];  // ()

    float* out  = (float*)d_out;                   // (1024, 128)
    float* neww = out + (size_t)SIZE * BATCH;      // (1024, 64, 1024)

    ctx_k<<<SIZE / SPER, 512>>>(proj, pbias, ctxin, logits);
    main_k<<<dim3(NSLOT / 8, SIZE), 256>>>(weights, targets, biasp, out, neww);
}